// round 1
// baseline (speedup 1.0000x reference)
#include <cuda_runtime.h>
#include <cuda_bf16.h>
#include <math.h>

#define NN 50000
#define EE 800000
#define DD 128
#define MAXN 4
#define SLOT_INF 0x7FFFFFFF
#define CONV_ITERS 16

// ---------------- scratch (device globals; no allocation allowed) ----------
__device__ int   g_slots[NN * MAXN];     // 4 smallest in-edge ids per node
__device__ float g_h[(size_t)NN * DD];   // pre-norm layer output
__device__ float g_blankp[DD];
__device__ float g_sum[DD];
__device__ float g_sq[DD];
__device__ float g_mu[DD];
__device__ float g_rstd[DD];

// ---------------- kernels ---------------------------------------------------

__global__ void init_slots_kernel() {
    int i = blockIdx.x * blockDim.x + threadIdx.x;
    if (i < NN * MAXN) g_slots[i] = SLOT_INF;
}

// Lock-free top-4-smallest edge-id per destination node via cascaded atomicMin.
__global__ void edge_pass_kernel(const int* __restrict__ dst) {
    int e = blockIdx.x * blockDim.x + threadIdx.x;
    if (e >= EE) return;
    int node = dst[e];
    int v = e;
    int* sl = &g_slots[node * MAXN];
#pragma unroll
    for (int k = 0; k < MAXN; k++) {
        int old = atomicMin(&sl[k], v);
        if (old == SLOT_INF) break;   // inserted into empty slot, nothing displaced
        v = max(v, old);              // displaced (larger) value cascades
    }
}

// blank_p = W @ blank + b ; also zero the stats accumulators for this layer.
__global__ void blankp_kernel(const float* __restrict__ W,
                              const float* __restrict__ b,
                              const float* __restrict__ blank) {
    int d = threadIdx.x;  // 128 threads
    float s = b[d];
#pragma unroll 8
    for (int j = 0; j < DD; j++) s += W[d * DD + j] * blank[j];
    g_blankp[d] = s;
    g_sum[d] = 0.0f;
    g_sq[d]  = 0.0f;
}

// Main conv: for each (node, dim) gather <=4 source values, sort-4, cw-dot,
// h = a*x + out. Accumulate per-dim sum / sumsq for batch norm.
__global__ __launch_bounds__(512) void conv_kernel(
    const float* __restrict__ x, const int* __restrict__ src,
    const float* __restrict__ cw, const float* __restrict__ cb,
    const float* __restrict__ a_p)
{
    int d   = threadIdx.x & 127;
    int sub = threadIdx.x >> 7;   // 0..3 node sub-lanes
    float c0 = __ldg(cw + 0), c1 = __ldg(cw + 1), c2 = __ldg(cw + 2), c3 = __ldg(cw + 3);
    float cbv = __ldg(cb);
    float av  = __ldg(a_p);
    float bp  = g_blankp[d];

    float lsum = 0.0f, lsq = 0.0f;
    int base = (blockIdx.x * 4 + sub) * CONV_ITERS;

#pragma unroll 4
    for (int it = 0; it < CONV_ITERS; it++) {
        int i = base + it;
        if (i < NN) {
            int4 s = *reinterpret_cast<const int4*>(&g_slots[i * 4]);
            float v0 = (s.x == SLOT_INF) ? bp : __ldg(&x[(size_t)__ldg(&src[s.x]) * DD + d]);
            float v1 = (s.y == SLOT_INF) ? bp : __ldg(&x[(size_t)__ldg(&src[s.y]) * DD + d]);
            float v2 = (s.z == SLOT_INF) ? bp : __ldg(&x[(size_t)__ldg(&src[s.z]) * DD + d]);
            float v3 = (s.w == SLOT_INF) ? bp : __ldg(&x[(size_t)__ldg(&src[s.w]) * DD + d]);
            // ascending sorting network (4 elems, 5 compare-exchanges)
            float t;
            t = fminf(v0, v1); v1 = fmaxf(v0, v1); v0 = t;
            t = fminf(v2, v3); v3 = fmaxf(v2, v3); v2 = t;
            t = fminf(v0, v2); v2 = fmaxf(v0, v2); v0 = t;
            t = fminf(v1, v3); v3 = fmaxf(v1, v3); v1 = t;
            t = fminf(v1, v2); v2 = fmaxf(v1, v2); v1 = t;
            float out = v0 * c0 + v1 * c1 + v2 * c2 + v3 * c3 + cbv;
            float hv  = av * x[(size_t)i * DD + d] + out;
            g_h[(size_t)i * DD + d] = hv;
            lsum += hv;
            lsq  += hv * hv;
        }
    }

    __shared__ float ssum[512];
    __shared__ float ssq[512];
    ssum[threadIdx.x] = lsum;
    ssq[threadIdx.x]  = lsq;
    __syncthreads();
    if (threadIdx.x < 128) {
        float a = ssum[d] + ssum[d + 128] + ssum[d + 256] + ssum[d + 384];
        float q = ssq[d]  + ssq[d + 128]  + ssq[d + 256]  + ssq[d + 384];
        atomicAdd(&g_sum[d], a);
        atomicAdd(&g_sq[d], q);
    }
}

__global__ void stats_kernel() {
    int d = threadIdx.x;  // 128
    float mu  = g_sum[d] * (1.0f / NN);
    float var = g_sq[d] * (1.0f / NN) - mu * mu;
    g_mu[d]   = mu;
    g_rstd[d] = rsqrtf(var + 1e-5f);
}

// x_out = x_in + (h - mu) * rstd * g + be   (float4 vectorized)
__global__ void apply_kernel(const float* __restrict__ xin,
                             const float* __restrict__ g,
                             const float* __restrict__ be,
                             float* __restrict__ xout)
{
    size_t idx = (size_t)blockIdx.x * blockDim.x + threadIdx.x;
    size_t i4  = idx * 4;
    if (i4 >= (size_t)NN * DD) return;
    int d0 = (int)(i4 & 127);
    float4 h4 = *reinterpret_cast<const float4*>(&g_h[i4]);
    float4 x4 = *reinterpret_cast<const float4*>(&xin[i4]);
    float4 o;
    o.x = x4.x + (h4.x - g_mu[d0 + 0]) * g_rstd[d0 + 0] * __ldg(&g[d0 + 0]) + __ldg(&be[d0 + 0]);
    o.y = x4.y + (h4.y - g_mu[d0 + 1]) * g_rstd[d0 + 1] * __ldg(&g[d0 + 1]) + __ldg(&be[d0 + 1]);
    o.z = x4.z + (h4.z - g_mu[d0 + 2]) * g_rstd[d0 + 2] * __ldg(&g[d0 + 2]) + __ldg(&be[d0 + 2]);
    o.w = x4.w + (h4.w - g_mu[d0 + 3]) * g_rstd[d0 + 3] * __ldg(&g[d0 + 3]) + __ldg(&be[d0 + 3]);
    *reinterpret_cast<float4*>(&xout[i4]) = o;
}

// ---------------- launch -----------------------------------------------------

extern "C" void kernel_launch(void* const* d_in, const int* in_sizes, int n_in,
                              void* d_out, int out_size)
{
    const float* x   = (const float*)d_in[0];
    const int*   ei  = (const int*)d_in[1];
    const int*   src = ei;        // edge_index[0]
    const int*   dst = ei + EE;   // edge_index[1]

    // per-layer params: base = 2 + 8*layer : W,b,cw,cb,a,g,be,blank
    const float* W0     = (const float*)d_in[2];
    const float* b0     = (const float*)d_in[3];
    const float* cw0    = (const float*)d_in[4];
    const float* cb0    = (const float*)d_in[5];
    const float* a0     = (const float*)d_in[6];
    const float* g0     = (const float*)d_in[7];
    const float* be0    = (const float*)d_in[8];
    const float* blank0 = (const float*)d_in[9];
    const float* W1     = (const float*)d_in[10];
    const float* b1     = (const float*)d_in[11];
    const float* cw1    = (const float*)d_in[12];
    const float* cb1    = (const float*)d_in[13];
    const float* a1     = (const float*)d_in[14];
    const float* g1     = (const float*)d_in[15];
    const float* be1    = (const float*)d_in[16];
    const float* blank1 = (const float*)d_in[17];

    float* out = (float*)d_out;

    const int conv_blocks  = (NN + 4 * CONV_ITERS - 1) / (4 * CONV_ITERS);
    const int apply_blocks = (int)(((size_t)NN * DD / 4 + 255) / 256);

    // slots depend only on edge_index: build once, reuse for both layers
    init_slots_kernel<<<(NN * MAXN + 255) / 256, 256>>>();
    edge_pass_kernel<<<(EE + 255) / 256, 256>>>(dst);

    // ---- layer 0 : reads x (input), writes x1 into d_out ----
    blankp_kernel<<<1, 128>>>(W0, b0, blank0);
    conv_kernel<<<conv_blocks, 512>>>(x, src, cw0, cb0, a0);
    stats_kernel<<<1, 128>>>();
    apply_kernel<<<apply_blocks, 256>>>(x, g0, be0, out);

    // ---- layer 1 : reads x1 from d_out, writes final into d_out (in-place elementwise) ----
    blankp_kernel<<<1, 128>>>(W1, b1, blank1);
    conv_kernel<<<conv_blocks, 512>>>(out, src, cw1, cb1, a1);
    stats_kernel<<<1, 128>>>();
    apply_kernel<<<apply_blocks, 256>>>(out, g1, be1, out);
}

// round 2
// speedup vs baseline: 1.3557x; 1.3557x over previous
#include <cuda_runtime.h>
#include <cuda_bf16.h>
#include <math.h>

#define NN 50000
#define EE 800000
#define DD 128
#define MAXN 4
#define SLOT_INF 0x7FFFFFFF
#define CITERS 16
#define SUBS 8                 // node sub-lanes per block (256 threads / 32 dim-groups)
#define NODES_PER_BLOCK (SUBS * CITERS)

// ---------------- scratch (device globals; no allocation allowed) ----------
__device__ int    g_slots[NN * MAXN];      // 4 smallest in-edge ids per node
__device__ int4   g_srcn[NN];              // 4 source NODE ids per node (-1 = empty)
__device__ float  g_h[(size_t)NN * DD];    // pre-norm layer output
__device__ float  g_blankp[2][DD];
__device__ float  g_sum[2][DD];
__device__ float  g_sq[2][DD];
__device__ float  g_mu[DD];
__device__ float  g_rstd[DD];

// ---------------- kernels ---------------------------------------------------

__global__ void init_slots_kernel() {
    int i = blockIdx.x * blockDim.x + threadIdx.x;
    if (i < NN * MAXN) g_slots[i] = SLOT_INF;
}

// Lock-free top-4-smallest edge-id per destination node via cascaded atomicMin.
__global__ void edge_pass_kernel(const int* __restrict__ dst) {
    int e = blockIdx.x * blockDim.x + threadIdx.x;
    if (e >= EE) return;
    int node = dst[e];
    int v = e;
    int* sl = &g_slots[node * MAXN];
#pragma unroll
    for (int k = 0; k < MAXN; k++) {
        int old = atomicMin(&sl[k], v);
        if (old == SLOT_INF) break;   // inserted into empty slot, nothing displaced
        v = max(v, old);              // displaced (larger) value cascades
    }
}

// Convert slot edge-ids -> source node ids; compute blank_p for BOTH layers;
// zero stats accumulators for both layers. One kernel, dispatch on blockIdx.
__global__ void prep_kernel(const int* __restrict__ src,
                            const float* __restrict__ W0, const float* __restrict__ b0,
                            const float* __restrict__ blank0,
                            const float* __restrict__ W1, const float* __restrict__ b1,
                            const float* __restrict__ blank1)
{
    int nconv = (NN + 255) / 256;
    if ((int)blockIdx.x < nconv) {
        int i = blockIdx.x * 256 + threadIdx.x;
        if (i < NN) {
            int4 s = *reinterpret_cast<const int4*>(&g_slots[i * 4]);
            int4 r;
            r.x = (s.x == SLOT_INF) ? -1 : __ldg(&src[s.x]);
            r.y = (s.y == SLOT_INF) ? -1 : __ldg(&src[s.y]);
            r.z = (s.z == SLOT_INF) ? -1 : __ldg(&src[s.z]);
            r.w = (s.w == SLOT_INF) ? -1 : __ldg(&src[s.w]);
            g_srcn[i] = r;
        }
    } else {
        // last block: blankp for both layers + zero stats
        int t = threadIdx.x;           // 0..255
        int layer = t >> 7;            // 0 or 1
        int d = t & 127;
        const float* W  = layer ? W1 : W0;
        const float* b  = layer ? b1 : b0;
        const float* bl = layer ? blank1 : blank0;
        float s = b[d];
#pragma unroll 8
        for (int j = 0; j < DD; j++) s += W[d * DD + j] * bl[j];
        g_blankp[layer][d] = s;
        g_sum[layer][d] = 0.0f;
        g_sq[layer][d]  = 0.0f;
    }
}

// Main conv: thread owns 4 dims (float4). Gather <=4 source rows, sort-4
// componentwise, cw-dot, h = a*x + out. Per-dim sum/sumsq partials.
__global__ __launch_bounds__(256) void conv_kernel(
    const float4* __restrict__ x4,
    const float* __restrict__ cw, const float* __restrict__ cb,
    const float* __restrict__ a_p, int layer)
{
    int dg  = threadIdx.x & 31;    // dim group: dims 4*dg .. 4*dg+3
    int sub = threadIdx.x >> 5;    // 0..7 node sub-lanes
    float c0 = __ldg(cw + 0), c1 = __ldg(cw + 1), c2 = __ldg(cw + 2), c3 = __ldg(cw + 3);
    float cbv = __ldg(cb);
    float av  = __ldg(a_p);
    float4 bp = *reinterpret_cast<const float4*>(&g_blankp[layer][dg * 4]);

    float4 lsum = make_float4(0.f, 0.f, 0.f, 0.f);
    float4 lsq  = make_float4(0.f, 0.f, 0.f, 0.f);
    int base = (blockIdx.x * SUBS + sub) * CITERS;
    float4* h4 = reinterpret_cast<float4*>(g_h);

#pragma unroll 4
    for (int it = 0; it < CITERS; it++) {
        int i = base + it;
        if (i < NN) {
            int4 s = g_srcn[i];
            float4 v0 = (s.x < 0) ? bp : __ldg(&x4[(size_t)s.x * 32 + dg]);
            float4 v1 = (s.y < 0) ? bp : __ldg(&x4[(size_t)s.y * 32 + dg]);
            float4 v2 = (s.z < 0) ? bp : __ldg(&x4[(size_t)s.z * 32 + dg]);
            float4 v3 = (s.w < 0) ? bp : __ldg(&x4[(size_t)s.w * 32 + dg]);
            float4 xv = x4[(size_t)i * 32 + dg];
            // componentwise ascending sort-4 (5 compare-exchanges per lane)
            float t;
#define CSWAP(A,B) \
            t = fminf(A.x,B.x); B.x = fmaxf(A.x,B.x); A.x = t; \
            t = fminf(A.y,B.y); B.y = fmaxf(A.y,B.y); A.y = t; \
            t = fminf(A.z,B.z); B.z = fmaxf(A.z,B.z); A.z = t; \
            t = fminf(A.w,B.w); B.w = fmaxf(A.w,B.w); A.w = t;
            CSWAP(v0, v1)
            CSWAP(v2, v3)
            CSWAP(v0, v2)
            CSWAP(v1, v3)
            CSWAP(v1, v2)
#undef CSWAP
            float4 hv;
            hv.x = av * xv.x + v0.x * c0 + v1.x * c1 + v2.x * c2 + v3.x * c3 + cbv;
            hv.y = av * xv.y + v0.y * c0 + v1.y * c1 + v2.y * c2 + v3.y * c3 + cbv;
            hv.z = av * xv.z + v0.z * c0 + v1.z * c1 + v2.z * c2 + v3.z * c3 + cbv;
            hv.w = av * xv.w + v0.w * c0 + v1.w * c1 + v2.w * c2 + v3.w * c3 + cbv;
            h4[(size_t)i * 32 + dg] = hv;
            lsum.x += hv.x; lsum.y += hv.y; lsum.z += hv.z; lsum.w += hv.w;
            lsq.x += hv.x * hv.x; lsq.y += hv.y * hv.y;
            lsq.z += hv.z * hv.z; lsq.w += hv.w * hv.w;
        }
    }

    __shared__ float4 ssum[256];
    __shared__ float4 ssq[256];
    ssum[threadIdx.x] = lsum;
    ssq[threadIdx.x]  = lsq;
    __syncthreads();
    if (threadIdx.x < 32) {
        float4 a = ssum[threadIdx.x];
        float4 q = ssq[threadIdx.x];
#pragma unroll
        for (int k = 1; k < SUBS; k++) {
            float4 a2 = ssum[threadIdx.x + 32 * k];
            float4 q2 = ssq[threadIdx.x + 32 * k];
            a.x += a2.x; a.y += a2.y; a.z += a2.z; a.w += a2.w;
            q.x += q2.x; q.y += q2.y; q.z += q2.z; q.w += q2.w;
        }
        int d0 = threadIdx.x * 4;
        atomicAdd(&g_sum[layer][d0 + 0], a.x);
        atomicAdd(&g_sum[layer][d0 + 1], a.y);
        atomicAdd(&g_sum[layer][d0 + 2], a.z);
        atomicAdd(&g_sum[layer][d0 + 3], a.w);
        atomicAdd(&g_sq[layer][d0 + 0], q.x);
        atomicAdd(&g_sq[layer][d0 + 1], q.y);
        atomicAdd(&g_sq[layer][d0 + 2], q.z);
        atomicAdd(&g_sq[layer][d0 + 3], q.w);
    }
}

__global__ void stats_kernel(int layer) {
    int d = threadIdx.x;  // 128
    float mu  = g_sum[layer][d] * (1.0f / NN);
    float var = g_sq[layer][d] * (1.0f / NN) - mu * mu;
    g_mu[d]   = mu;
    g_rstd[d] = rsqrtf(var + 1e-5f);
}

// x_out = x_in + (h - mu) * rstd * g + be   (float4 vectorized)
__global__ void apply_kernel(const float* __restrict__ xin,
                             const float* __restrict__ g,
                             const float* __restrict__ be,
                             float* __restrict__ xout)
{
    size_t idx = (size_t)blockIdx.x * blockDim.x + threadIdx.x;
    size_t i4  = idx * 4;
    if (i4 >= (size_t)NN * DD) return;
    int d0 = (int)(i4 & 127);
    float4 h4 = *reinterpret_cast<const float4*>(&g_h[i4]);
    float4 x4 = *reinterpret_cast<const float4*>(&xin[i4]);
    float4 o;
    o.x = x4.x + (h4.x - g_mu[d0 + 0]) * g_rstd[d0 + 0] * __ldg(&g[d0 + 0]) + __ldg(&be[d0 + 0]);
    o.y = x4.y + (h4.y - g_mu[d0 + 1]) * g_rstd[d0 + 1] * __ldg(&g[d0 + 1]) + __ldg(&be[d0 + 1]);
    o.z = x4.z + (h4.z - g_mu[d0 + 2]) * g_rstd[d0 + 2] * __ldg(&g[d0 + 2]) + __ldg(&be[d0 + 2]);
    o.w = x4.w + (h4.w - g_mu[d0 + 3]) * g_rstd[d0 + 3] * __ldg(&g[d0 + 3]) + __ldg(&be[d0 + 3]);
    *reinterpret_cast<float4*>(&xout[i4]) = o;
}

// ---------------- launch -----------------------------------------------------

extern "C" void kernel_launch(void* const* d_in, const int* in_sizes, int n_in,
                              void* d_out, int out_size)
{
    const float* x   = (const float*)d_in[0];
    const int*   ei  = (const int*)d_in[1];
    const int*   src = ei;        // edge_index[0]
    const int*   dst = ei + EE;   // edge_index[1]

    const float* W0     = (const float*)d_in[2];
    const float* b0     = (const float*)d_in[3];
    const float* cw0    = (const float*)d_in[4];
    const float* cb0    = (const float*)d_in[5];
    const float* a0     = (const float*)d_in[6];
    const float* g0     = (const float*)d_in[7];
    const float* be0    = (const float*)d_in[8];
    const float* blank0 = (const float*)d_in[9];
    const float* W1     = (const float*)d_in[10];
    const float* b1     = (const float*)d_in[11];
    const float* cw1    = (const float*)d_in[12];
    const float* cb1    = (const float*)d_in[13];
    const float* a1     = (const float*)d_in[14];
    const float* g1     = (const float*)d_in[15];
    const float* be1    = (const float*)d_in[16];
    const float* blank1 = (const float*)d_in[17];

    float* out = (float*)d_out;

    const int conv_blocks  = (NN + NODES_PER_BLOCK - 1) / NODES_PER_BLOCK;
    const int apply_blocks = (int)(((size_t)NN * DD / 4 + 255) / 256);
    const int prep_blocks  = (NN + 255) / 256 + 1;

    // slots depend only on edge_index: build once, reuse for both layers
    init_slots_kernel<<<(NN * MAXN + 255) / 256, 256>>>();
    edge_pass_kernel<<<(EE + 255) / 256, 256>>>(dst);
    prep_kernel<<<prep_blocks, 256>>>(src, W0, b0, blank0, W1, b1, blank1);

    // ---- layer 0 : reads x (input), writes x1 into d_out ----
    conv_kernel<<<conv_blocks, 256>>>((const float4*)x, cw0, cb0, a0, 0);
    stats_kernel<<<1, 128>>>(0);
    apply_kernel<<<apply_blocks, 256>>>(x, g0, be0, out);

    // ---- layer 1 : reads x1 from d_out, writes final into d_out ----
    conv_kernel<<<conv_blocks, 256>>>((const float4*)out, cw1, cb1, a1, 1);
    stats_kernel<<<1, 128>>>(1);
    apply_kernel<<<apply_blocks, 256>>>(out, g1, be1, out);
}

// round 3
// speedup vs baseline: 1.3747x; 1.0140x over previous
#include <cuda_runtime.h>
#include <cuda_bf16.h>
#include <math.h>

#define NN 50000
#define EE 800000
#define DD 128
#define MAXN 4
#define SLOT_INF 0xFFFFFFFFu
#define CITERS 8
#define SUBS 8                 // node sub-lanes per block (256 threads / 32 dim-groups)
#define NODES_PER_BLOCK (SUBS * CITERS)

// ---------------- scratch (device globals; no allocation allowed) ----------
__device__ unsigned g_slots[NN * MAXN];    // 4 smallest in-edge ids per node
__device__ int4     g_srcn[NN];            // 4 source NODE ids per node (-1 = empty)
__device__ float    g_h[(size_t)NN * DD];  // pre-norm layer output
__device__ float    g_blankp[2][DD];
__device__ float    g_sum[2][DD];
__device__ float    g_sq[2][DD];

// ---------------- kernels ---------------------------------------------------

// Lock-free top-4-smallest edge-id per destination node via cascaded atomicMin.
// 4 edges per thread (int4 loads).
__global__ void edge_pass_kernel(const int4* __restrict__ dst4) {
    int t = blockIdx.x * blockDim.x + threadIdx.x;
    if (t >= EE / 4) return;
    int4 d = __ldg(&dst4[t]);
    int e0 = t * 4;
#pragma unroll
    for (int j = 0; j < 4; j++) {
        int node = (j == 0) ? d.x : (j == 1) ? d.y : (j == 2) ? d.z : d.w;
        unsigned v = (unsigned)(e0 + j);
        unsigned* sl = &g_slots[node * MAXN];
#pragma unroll
        for (int k = 0; k < MAXN; k++) {
            unsigned old = atomicMin(&sl[k], v);
            if (old == SLOT_INF) break;   // inserted into empty slot
            v = max(v, old);              // displaced (larger) value cascades
        }
    }
}

// Convert slot edge-ids -> source node ids; compute blank_p for BOTH layers;
// zero stats accumulators for both layers. One kernel, dispatch on blockIdx.
__global__ void prep_kernel(const int* __restrict__ src,
                            const float* __restrict__ W0, const float* __restrict__ b0,
                            const float* __restrict__ blank0,
                            const float* __restrict__ W1, const float* __restrict__ b1,
                            const float* __restrict__ blank1)
{
    int nconv = (NN + 255) / 256;
    if ((int)blockIdx.x < nconv) {
        int i = blockIdx.x * 256 + threadIdx.x;
        if (i < NN) {
            uint4 s = *reinterpret_cast<const uint4*>(&g_slots[i * 4]);
            int4 r;
            r.x = (s.x == SLOT_INF) ? -1 : __ldg(&src[s.x]);
            r.y = (s.y == SLOT_INF) ? -1 : __ldg(&src[s.y]);
            r.z = (s.z == SLOT_INF) ? -1 : __ldg(&src[s.z]);
            r.w = (s.w == SLOT_INF) ? -1 : __ldg(&src[s.w]);
            g_srcn[i] = r;
        }
    } else {
        // last block: blankp for both layers + zero stats
        int t = threadIdx.x;           // 0..255
        int layer = t >> 7;            // 0 or 1
        int d = t & 127;
        const float* W  = layer ? W1 : W0;
        const float* b  = layer ? b1 : b0;
        const float* bl = layer ? blank1 : blank0;
        float s = b[d];
#pragma unroll 8
        for (int j = 0; j < DD; j++) s += W[d * DD + j] * bl[j];
        g_blankp[layer][d] = s;
        g_sum[layer][d] = 0.0f;
        g_sq[layer][d]  = 0.0f;
    }
}

// Main conv: thread owns 4 dims (float4). Gather <=4 source rows, sort-4
// componentwise, cw-dot, h = a*x + out. Per-dim sum/sumsq partials.
// Slot int4 for next iteration is prefetched to overlap the index->gather chain.
__global__ __launch_bounds__(256) void conv_kernel(
    const float4* __restrict__ x4,
    const float* __restrict__ cw, const float* __restrict__ cb,
    const float* __restrict__ a_p, int layer)
{
    int dg  = threadIdx.x & 31;    // dim group: dims 4*dg .. 4*dg+3
    int sub = threadIdx.x >> 5;    // 0..7 node sub-lanes
    float c0 = __ldg(cw + 0), c1 = __ldg(cw + 1), c2 = __ldg(cw + 2), c3 = __ldg(cw + 3);
    float cbv = __ldg(cb);
    float av  = __ldg(a_p);
    float4 bp = *reinterpret_cast<const float4*>(&g_blankp[layer][dg * 4]);

    float4 lsum = make_float4(0.f, 0.f, 0.f, 0.f);
    float4 lsq  = make_float4(0.f, 0.f, 0.f, 0.f);
    int base = (blockIdx.x * SUBS + sub) * CITERS;
    float4* h4 = reinterpret_cast<float4*>(g_h);

    int4 s = (base < NN) ? g_srcn[base] : make_int4(-1, -1, -1, -1);

#pragma unroll 4
    for (int it = 0; it < CITERS; it++) {
        int i = base + it;
        // prefetch next slot record before the dependent gathers
        int4 snext = (it + 1 < CITERS && i + 1 < NN) ? g_srcn[i + 1]
                                                     : make_int4(-1, -1, -1, -1);
        if (i < NN) {
            float4 v0 = (s.x < 0) ? bp : __ldg(&x4[(size_t)s.x * 32 + dg]);
            float4 v1 = (s.y < 0) ? bp : __ldg(&x4[(size_t)s.y * 32 + dg]);
            float4 v2 = (s.z < 0) ? bp : __ldg(&x4[(size_t)s.z * 32 + dg]);
            float4 v3 = (s.w < 0) ? bp : __ldg(&x4[(size_t)s.w * 32 + dg]);
            float4 xv = __ldg(&x4[(size_t)i * 32 + dg]);
            // componentwise ascending sort-4 (5 compare-exchanges per lane)
            float t;
#define CSWAP(A,B) \
            t = fminf(A.x,B.x); B.x = fmaxf(A.x,B.x); A.x = t; \
            t = fminf(A.y,B.y); B.y = fmaxf(A.y,B.y); A.y = t; \
            t = fminf(A.z,B.z); B.z = fmaxf(A.z,B.z); A.z = t; \
            t = fminf(A.w,B.w); B.w = fmaxf(A.w,B.w); A.w = t;
            CSWAP(v0, v1)
            CSWAP(v2, v3)
            CSWAP(v0, v2)
            CSWAP(v1, v3)
            CSWAP(v1, v2)
#undef CSWAP
            float4 hv;
            hv.x = av * xv.x + v0.x * c0 + v1.x * c1 + v2.x * c2 + v3.x * c3 + cbv;
            hv.y = av * xv.y + v0.y * c0 + v1.y * c1 + v2.y * c2 + v3.y * c3 + cbv;
            hv.z = av * xv.z + v0.z * c0 + v1.z * c1 + v2.z * c2 + v3.z * c3 + cbv;
            hv.w = av * xv.w + v0.w * c0 + v1.w * c1 + v2.w * c2 + v3.w * c3 + cbv;
            h4[(size_t)i * 32 + dg] = hv;
            lsum.x += hv.x; lsum.y += hv.y; lsum.z += hv.z; lsum.w += hv.w;
            lsq.x += hv.x * hv.x; lsq.y += hv.y * hv.y;
            lsq.z += hv.z * hv.z; lsq.w += hv.w * hv.w;
        }
        s = snext;
    }

    __shared__ float4 ssum[256];
    __shared__ float4 ssq[256];
    ssum[threadIdx.x] = lsum;
    ssq[threadIdx.x]  = lsq;
    __syncthreads();
    if (threadIdx.x < 32) {
        float4 a = ssum[threadIdx.x];
        float4 q = ssq[threadIdx.x];
#pragma unroll
        for (int k = 1; k < SUBS; k++) {
            float4 a2 = ssum[threadIdx.x + 32 * k];
            float4 q2 = ssq[threadIdx.x + 32 * k];
            a.x += a2.x; a.y += a2.y; a.z += a2.z; a.w += a2.w;
            q.x += q2.x; q.y += q2.y; q.z += q2.z; q.w += q2.w;
        }
        int d0 = threadIdx.x * 4;
        atomicAdd(&g_sum[layer][d0 + 0], a.x);
        atomicAdd(&g_sum[layer][d0 + 1], a.y);
        atomicAdd(&g_sum[layer][d0 + 2], a.z);
        atomicAdd(&g_sum[layer][d0 + 3], a.w);
        atomicAdd(&g_sq[layer][d0 + 0], q.x);
        atomicAdd(&g_sq[layer][d0 + 1], q.y);
        atomicAdd(&g_sq[layer][d0 + 2], q.z);
        atomicAdd(&g_sq[layer][d0 + 3], q.w);
    }
}

// x_out = x_in + (h - mu) * rstd * g + be, with mu/rstd derived per-block
// from the global accumulators (fused stats; no separate stats kernel).
__global__ __launch_bounds__(256) void apply_kernel(
    const float* __restrict__ xin,
    const float* __restrict__ g,
    const float* __restrict__ be,
    float* __restrict__ xout, int layer)
{
    __shared__ float smu[DD];
    __shared__ float sscale[DD];   // rstd * g
    if (threadIdx.x < DD) {
        int d = threadIdx.x;
        float mu  = g_sum[layer][d] * (1.0f / NN);
        float var = g_sq[layer][d] * (1.0f / NN) - mu * mu;
        smu[d]    = mu;
        sscale[d] = rsqrtf(var + 1e-5f) * __ldg(&g[d]);
    }
    __syncthreads();

    size_t idx = (size_t)blockIdx.x * blockDim.x + threadIdx.x;
    size_t i4  = idx * 4;
    if (i4 >= (size_t)NN * DD) return;
    int d0 = (int)(i4 & 127);
    float4 h4 = *reinterpret_cast<const float4*>(&g_h[i4]);
    float4 x4 = *reinterpret_cast<const float4*>(&xin[i4]);
    float4 o;
    o.x = x4.x + (h4.x - smu[d0 + 0]) * sscale[d0 + 0] + __ldg(&be[d0 + 0]);
    o.y = x4.y + (h4.y - smu[d0 + 1]) * sscale[d0 + 1] + __ldg(&be[d0 + 1]);
    o.z = x4.z + (h4.z - smu[d0 + 2]) * sscale[d0 + 2] + __ldg(&be[d0 + 2]);
    o.w = x4.w + (h4.w - smu[d0 + 3]) * sscale[d0 + 3] + __ldg(&be[d0 + 3]);
    *reinterpret_cast<float4*>(&xout[i4]) = o;
}

// ---------------- launch -----------------------------------------------------

extern "C" void kernel_launch(void* const* d_in, const int* in_sizes, int n_in,
                              void* d_out, int out_size)
{
    const float* x   = (const float*)d_in[0];
    const int*   ei  = (const int*)d_in[1];
    const int*   src = ei;        // edge_index[0]
    const int*   dst = ei + EE;   // edge_index[1]

    const float* W0     = (const float*)d_in[2];
    const float* b0     = (const float*)d_in[3];
    const float* cw0    = (const float*)d_in[4];
    const float* cb0    = (const float*)d_in[5];
    const float* a0     = (const float*)d_in[6];
    const float* g0     = (const float*)d_in[7];
    const float* be0    = (const float*)d_in[8];
    const float* blank0 = (const float*)d_in[9];
    const float* W1     = (const float*)d_in[10];
    const float* b1     = (const float*)d_in[11];
    const float* cw1    = (const float*)d_in[12];
    const float* cb1    = (const float*)d_in[13];
    const float* a1     = (const float*)d_in[14];
    const float* g1     = (const float*)d_in[15];
    const float* be1    = (const float*)d_in[16];
    const float* blank1 = (const float*)d_in[17];

    float* out = (float*)d_out;

    const int conv_blocks  = (NN + NODES_PER_BLOCK - 1) / NODES_PER_BLOCK;
    const int apply_blocks = (int)(((size_t)NN * DD / 4 + 255) / 256);
    const int prep_blocks  = (NN + 255) / 256 + 1;

    // slots init: 0xFF byte pattern == SLOT_INF (unsigned), via async memset
    void* slots_ptr = nullptr;
    cudaGetSymbolAddress(&slots_ptr, g_slots);
    cudaMemsetAsync(slots_ptr, 0xFF, sizeof(unsigned) * NN * MAXN);

    edge_pass_kernel<<<(EE / 4 + 255) / 256, 256>>>((const int4*)dst);
    prep_kernel<<<prep_blocks, 256>>>(src, W0, b0, blank0, W1, b1, blank1);

    // ---- layer 0 : reads x (input), writes x1 into d_out ----
    conv_kernel<<<conv_blocks, 256>>>((const float4*)x, cw0, cb0, a0, 0);
    apply_kernel<<<apply_blocks, 256>>>(x, g0, be0, out, 0);

    // ---- layer 1 : reads x1 from d_out, writes final into d_out ----
    conv_kernel<<<conv_blocks, 256>>>((const float4*)out, cw1, cb1, a1, 1);
    apply_kernel<<<apply_blocks, 256>>>(out, g1, be1, out, 1);
}